// round 16
// baseline (speedup 1.0000x reference)
#include <cuda_runtime.h>
#include <cuda_bf16.h>
#include <math.h>
#include <stdint.h>

#define NB   32
#define NP   2048
#define KNN  20
#define HDIM 128
#define HID  256
#define NTOT (NB*NP)
#define EPSBN 1e-5f

// ---------------- scratch (static device globals; no allocation) ----------------
__device__ int   g_nbr[NTOT*KNN];
__device__ float g_h0[(size_t)NTOT*HDIM];
__device__ float g_h1[(size_t)NTOT*HDIM];
// pre-split (bf16 hi/lo), pre-swizzled weights: [layer][half][hi=0/lo=1][128*128]
__device__ __nv_bfloat16 g_w1b[2][2][2][16384];
__device__ __nv_bfloat16 g_w2b[2][2][2][16384];

// ---------------- helpers -------------------------------------------------------
__device__ __forceinline__ uint32_t smem_u32(const void* p) {
    uint32_t a;
    asm("{ .reg .u64 t; cvta.to.shared.u64 t, %1; cvt.u32.u64 %0, t; }" : "=r"(a) : "l"(p));
    return a;
}
__device__ __forceinline__ uint32_t pkbf(float lo, float hi) {
    uint32_t r; asm("cvt.rn.bf16x2.f32 %0, %1, %2;" : "=r"(r) : "f"(hi), "f"(lo)); return r;
}
__device__ __forceinline__ float bfhi(float v) {
    return __bfloat162float(__float2bfloat16_rn(v));
}
__device__ __forceinline__ void mma16816(float (&c)[4], const uint32_t (&a)[4],
                                         uint32_t b0, uint32_t b1) {
    asm volatile(
        "mma.sync.aligned.m16n8k16.row.col.f32.bf16.bf16.f32 "
        "{%0,%1,%2,%3}, {%4,%5,%6,%7}, {%8,%9}, {%0,%1,%2,%3};"
        : "+f"(c[0]), "+f"(c[1]), "+f"(c[2]), "+f"(c[3])
        : "r"(a[0]), "r"(a[1]), "r"(a[2]), "r"(a[3]), "r"(b0), "r"(b1));
}
__device__ __forceinline__ void ldmA(uint32_t (&a)[4], uint32_t base, int m0, int k0, int lane) {
    int row = m0 + (lane & 15);
    int ch  = (k0 >> 3) + (lane >> 4);
    uint32_t addr = base + row*256 + (((ch ^ (row & 7)) & 15) << 4);
    asm volatile("ldmatrix.sync.aligned.m8n8.x4.shared.b16 {%0,%1,%2,%3}, [%4];"
                 : "=r"(a[0]), "=r"(a[1]), "=r"(a[2]), "=r"(a[3]) : "r"(addr));
}
__device__ __forceinline__ void ldmBt(uint32_t (&b)[4], uint32_t base, int k0, int n0, int lane) {
    int k = k0 + (lane & 7) + ((lane >> 3) & 1) * 8;
    int n = n0 + ((lane >> 4) & 1) * 8;
    uint32_t addr = base + k*256 + ((((n >> 3) ^ (k & 7)) & 15) << 4);
    asm volatile("ldmatrix.sync.aligned.m8n8.x4.trans.shared.b16 {%0,%1,%2,%3}, [%4];"
                 : "=r"(b[0]), "=r"(b[1]), "=r"(b[2]), "=r"(b[3]) : "r"(addr));
}

// ================================================================= kNN =========
// FROZEN at the R8/R11-proven version: one query per thread, SMEM broadcast,
// deferred index-stack inserts, bubble only in synchronized drains.
#define KBLK 128
#define KCAP 32
#define KNN_SMEM_BYTES (NP*16 + KCAP*KBLK*4)   // 49152
__global__ __launch_bounds__(KBLK)
void knn_kernel(const float* __restrict__ x)
{
    extern __shared__ float4 sc[];
    int* sbi = (int*)(sc + NP);
    const int b    = blockIdx.x >> 4;
    const int tile = blockIdx.x & 15;
    const int tid  = threadIdx.x;

    const float* xb = x + (size_t)b*NP*3;
    for (int i = tid; i < NP; i += KBLK) {
        float a0 = xb[i*3+0], a1 = xb[i*3+1], a2 = xb[i*3+2];
        sc[i] = make_float4(a0, a1, a2, a0*a0 + a1*a1 + a2*a2);
    }
    __syncthreads();

    const int q = tile*KBLK + tid;
    const float4 qc = sc[q];

    float d[KNN]; int id[KNN];
#pragma unroll
    for (int j = 0; j < KNN; j++) { d[j] = INFINITY; id[j] = -1; }
    float worst = INFINITY;
    int cnt = 0;

    for (int c0 = 0; c0 < NP; c0 += 4) {
#pragma unroll
        for (int u = 0; u < 4; u++) {
            int c = c0 + u;
            float4 cc = sc[c];
            float dot  = qc.x*cc.x + qc.y*cc.y + qc.z*cc.z;
            float dist = qc.w + cc.w - 2.0f*dot;
            if (dist < worst) { sbi[cnt*KBLK + tid] = c; cnt++; }
        }
        if (__any_sync(0xffffffffu, cnt >= KCAP-4)) {
            for (int j = 0; ; j++) {
                if (!__any_sync(0xffffffffu, j < cnt)) break;
                float dd = INFINITY; int ii = 0;
                if (j < cnt) {
                    ii = sbi[j*KBLK + tid];
                    float4 cc = sc[ii];
                    float dot = qc.x*cc.x + qc.y*cc.y + qc.z*cc.z;
                    dd = qc.w + cc.w - 2.0f*dot;
                }
                if (dd < worst) {
                    float vd = dd; int vi = ii;
#pragma unroll
                    for (int t = 0; t < KNN; t++) {
                        if (vd < d[t]) {
                            float td = d[t]; int ti = id[t];
                            d[t] = vd; id[t] = vi; vd = td; vi = ti;
                        }
                    }
                    worst = d[KNN-1];
                }
            }
            cnt = 0;
        }
    }
    for (int j = 0; ; j++) {
        if (!__any_sync(0xffffffffu, j < cnt)) break;
        float dd = INFINITY; int ii = 0;
        if (j < cnt) {
            ii = sbi[j*KBLK + tid];
            float4 cc = sc[ii];
            float dot = qc.x*cc.x + qc.y*cc.y + qc.z*cc.z;
            dd = qc.w + cc.w - 2.0f*dot;
        }
        if (dd < worst) {
            float vd = dd; int vi = ii;
#pragma unroll
            for (int t = 0; t < KNN; t++) {
                if (vd < d[t]) {
                    float td = d[t]; int ti = id[t];
                    d[t] = vd; id[t] = vi; vd = td; vi = ti;
                }
            }
            worst = d[KNN-1];
        }
    }

    int* outp = g_nbr + ((size_t)b*NP + q)*KNN;
#pragma unroll
    for (int j = 0; j < KNN; j++) outp[j] = b*NP + id[j];
}

// ============================================================ transfer =========
__global__ void transfer_kernel(const float* __restrict__ x,
                                const float* __restrict__ Wt,
                                const float* __restrict__ bt)
{
    int idx = blockIdx.x * blockDim.x + threadIdx.x;
    int n = idx >> 7, f = idx & (HDIM-1);
    float x0 = x[n*3+0], x1 = x[n*3+1], x2 = x[n*3+2];
    g_h0[idx] = bt[f] + x0*Wt[f] + x1*Wt[HDIM+f] + x2*Wt[2*HDIM+f];
}

// ============================================================ weight prep ======
__global__ void prep_w_kernel(const float* __restrict__ W1_0, const float* __restrict__ W2_0,
                              const float* __restrict__ W1_1, const float* __restrict__ W2_1)
{
    int idx = blockIdx.x * blockDim.x + threadIdx.x;   // 0..131071
    int layer = idx >> 16;
    int rem = idx & 65535;
    const float* W1 = layer ? W1_1 : W1_0;
    const float* W2 = layer ? W2_1 : W2_0;
    if (rem < 32768) {                       // W1 [k=128][n=256]
        int k = rem >> 8, n = rem & 255;
        float v = W1[k*HID + n];
        int h = n >> 7, nl = n & 127;
        int dst = k*128 + (((nl >> 3) ^ (k & 7)) << 3) + (nl & 7);
        __nv_bfloat16 hb = __float2bfloat16_rn(v);
        g_w1b[layer][h][0][dst] = hb;
        g_w1b[layer][h][1][dst] = __float2bfloat16_rn(v - __bfloat162float(hb));
    } else {                                 // W2 [K=256][n=128]
        int r2 = rem - 32768;
        int K = r2 >> 7, n = r2 & 127;
        float v = W2[K*HDIM + n];
        int h = K >> 7, kl = K & 127;
        int dst = kl*128 + (((n >> 3) ^ (kl & 7)) << 3) + (n & 7);
        __nv_bfloat16 hb = __float2bfloat16_rn(v);
        g_w2b[layer][h][0][dst] = hb;
        g_w2b[layer][h][1][dst] = __float2bfloat16_rn(v - __bfloat162float(hb));
    }
}

// ============================================================ GIN layer (mma.sync)
// 64-row blocks, 256 threads (8 warps as 2x4, warp tile 32x32), 2 blocks/SM.
// Single 32K W buffer: bf16x3 passes grouped by W operand —
// (Ahi·Whi, Alo·Whi) with W_hi staged, then (Ahi·Wlo) after restage.
#define GROWS 64
#define GT_THREADS 256
#define OFF_AHI  2048
#define OFF_ALO  (OFF_AHI + 16384)
#define OFF_THI  (OFF_ALO + 16384)
#define OFF_TLO  (OFF_THI + 16384)
#define OFF_W    (OFF_TLO + 16384)
#define GT_SMEM  (OFF_W + 32768)             // 100352 -> 2 blocks/SM

__device__ __forceinline__ void stage_w(char* smem, const __nv_bfloat16* __restrict__ src,
                                        int tid) {
    const float4* s = (const float4*)src;
    float4* d = (float4*)(smem + OFF_W);
#pragma unroll
    for (int i = 0; i < 8; i++) d[tid + i*GT_THREADS] = s[tid + i*GT_THREADS];
}
__device__ __forceinline__ void gemm_pass(float (&c)[2][4][4], uint32_t Abase,
                                          uint32_t Wbase, int lane, int wm, int wn) {
#pragma unroll
    for (int ks = 0; ks < 8; ks++) {
        uint32_t a0[4], a1[4];
        ldmA(a0, Abase, wm*32,      ks*16, lane);
        ldmA(a1, Abase, wm*32 + 16, ks*16, lane);
#pragma unroll
        for (int np = 0; np < 2; np++) {
            uint32_t b4[4];
            ldmBt(b4, Wbase, ks*16, wn*32 + np*16, lane);
#pragma unroll
            for (int n2 = 0; n2 < 2; n2++) {
                mma16816(c[0][np*2+n2], a0, b4[n2*2], b4[n2*2+1]);
                mma16816(c[1][np*2+n2], a1, b4[n2*2], b4[n2*2+1]);
            }
        }
    }
}

__global__ __launch_bounds__(GT_THREADS, 2)
void gin_mma_kernel(const float* __restrict__ hin, float* __restrict__ hout, int layer,
                    const float* __restrict__ b1v, const float* __restrict__ b2v,
                    const float* __restrict__ gw, const float* __restrict__ bb,
                    const float* __restrict__ rm, const float* __restrict__ rv,
                    int relu_out)
{
    extern __shared__ char smem[];
    const uint32_t smb = smem_u32(smem);
    const int tid  = threadIdx.x;
    const int wid  = tid >> 5;
    const int lane = tid & 31;
    const int wm   = wid >> 2;            // 0..1 -> rows wm*32
    const int wn   = wid & 3;             // 0..3 -> cols wn*32
    const int g    = lane >> 2;
    const int t4   = lane & 3;
    const int row0 = blockIdx.x * GROWS;

    float* s_b1    = (float*)(smem);
    float* s_scale = (float*)(smem + 1024);
    float* s_shift = (float*)(smem + 1536);
    int*   s_nbr   = (int*)(smem + OFF_W);    // overlay, gather phase only

    for (int i = tid; i < HID; i += GT_THREADS) s_b1[i] = b1v[i];
    if (tid < HDIM) {
        float sc = gw[tid] * rsqrtf(rv[tid] + EPSBN);
        s_scale[tid] = sc;
        s_shift[tid] = bb[tid] - sc * rm[tid];
    }
    for (int i = tid; i < GROWS*KNN; i += GT_THREADS)
        s_nbr[i] = g_nbr[(size_t)row0*KNN + i];
    __syncthreads();

    // ---- gather-max + bf16 hi/lo split into swizzled A ----
    for (int r = wid; r < GROWS; r += 8) {
        int row = row0 + r;
        float4 m = __ldg((const float4*)&hin[(size_t)row*HDIM + lane*4]);
#pragma unroll 4
        for (int k = 0; k < KNN; k++) {
            int nb = s_nbr[r*KNN + k];
            float4 v = __ldg((const float4*)&hin[(size_t)nb*HDIM + lane*4]);
            m.x = fmaxf(m.x, v.x); m.y = fmaxf(m.y, v.y);
            m.z = fmaxf(m.z, v.z); m.w = fmaxf(m.w, v.w);
        }
        float h0 = bfhi(m.x), h1 = bfhi(m.y), h2 = bfhi(m.z), h3 = bfhi(m.w);
        int ab = r*256 + ((((lane >> 1) ^ (r & 7)) & 15) << 4) + (lane & 1)*8;
        *(uint2*)(smem + OFF_AHI + ab) = make_uint2(pkbf(m.x, m.y), pkbf(m.z, m.w));
        *(uint2*)(smem + OFF_ALO + ab) =
            make_uint2(pkbf(m.x - h0, m.y - h1), pkbf(m.z - h2, m.w - h3));
    }
    __syncthreads();   // gather done; s_nbr overlay free

    float c2[2][4][4];
#pragma unroll
    for (int mt = 0; mt < 2; mt++)
#pragma unroll
        for (int nt = 0; nt < 4; nt++) {
            int cb = wn*32 + nt*8 + 2*t4;
            c2[mt][nt][0] = b2v[cb];  c2[mt][nt][1] = b2v[cb+1];
            c2[mt][nt][2] = b2v[cb];  c2[mt][nt][3] = b2v[cb+1];
        }

    const uint32_t Ah = smb + OFF_AHI, Al = smb + OFF_ALO;
    const uint32_t Th = smb + OFF_THI, Tl = smb + OFF_TLO;
    const uint32_t W  = smb + OFF_W;

    for (int h = 0; h < 2; h++) {
        // ---- GEMM1: c1 = A @ W1h (+b1), passes grouped by W operand ----
        float c1[2][4][4];
#pragma unroll
        for (int mt = 0; mt < 2; mt++)
#pragma unroll
            for (int nt = 0; nt < 4; nt++) {
                int cb = h*128 + wn*32 + nt*8 + 2*t4;
                c1[mt][nt][0] = s_b1[cb];  c1[mt][nt][1] = s_b1[cb+1];
                c1[mt][nt][2] = s_b1[cb];  c1[mt][nt][3] = s_b1[cb+1];
            }
        stage_w(smem, g_w1b[layer][h][0], tid);
        __syncthreads();
        gemm_pass(c1, Ah, W, lane, wm, wn);      // hi·hi
        gemm_pass(c1, Al, W, lane, wm, wn);      // lo·hi
        __syncthreads();
        stage_w(smem, g_w1b[layer][h][1], tid);
        __syncthreads();
        gemm_pass(c1, Ah, W, lane, wm, wn);      // hi·lo

        // ---- t1 = relu(c1): split to T (swizzled) ----
#pragma unroll
        for (int mt = 0; mt < 2; mt++)
#pragma unroll
            for (int nt = 0; nt < 4; nt++) {
                int r0 = wm*32 + mt*16 + g;
                int r1 = r0 + 8;
                int cl = wn*32 + nt*8 + 2*t4;
                float v0 = fmaxf(c1[mt][nt][0], 0.f), v1 = fmaxf(c1[mt][nt][1], 0.f);
                float v2 = fmaxf(c1[mt][nt][2], 0.f), v3 = fmaxf(c1[mt][nt][3], 0.f);
                float h0 = bfhi(v0), h1 = bfhi(v1), h2 = bfhi(v2), h3 = bfhi(v3);
                int by0 = r0*256 + ((((cl >> 3) ^ (r0 & 7)) & 15) << 4) + (cl & 7)*2;
                int by1 = r1*256 + ((((cl >> 3) ^ (r1 & 7)) & 15) << 4) + (cl & 7)*2;
                *(uint32_t*)(smem + OFF_THI + by0) = pkbf(v0, v1);
                *(uint32_t*)(smem + OFF_TLO + by0) = pkbf(v0 - h0, v1 - h1);
                *(uint32_t*)(smem + OFF_THI + by1) = pkbf(v2, v3);
                *(uint32_t*)(smem + OFF_TLO + by1) = pkbf(v2 - h2, v3 - h3);
            }
        __syncthreads();   // t1 visible; W1-lo reads done

        // ---- GEMM2: c2 += t1 @ W2h ----
        stage_w(smem, g_w2b[layer][h][0], tid);
        __syncthreads();
        gemm_pass(c2, Th, W, lane, wm, wn);      // hi·hi
        gemm_pass(c2, Tl, W, lane, wm, wn);      // lo·hi
        __syncthreads();
        stage_w(smem, g_w2b[layer][h][1], tid);
        __syncthreads();
        gemm_pass(c2, Th, W, lane, wm, wn);      // hi·lo
        __syncthreads();   // W2-lo reads done before next h stages / T rewrite
    }

    // ---- BN (+opt ReLU), direct STG.64 ----
#pragma unroll
    for (int mt = 0; mt < 2; mt++)
#pragma unroll
        for (int nt = 0; nt < 4; nt++) {
            int row = row0 + wm*32 + mt*16 + g;
            int col = wn*32 + nt*8 + 2*t4;
            float s0 = s_scale[col], s1 = s_scale[col+1];
            float t0 = s_shift[col], t1 = s_shift[col+1];
            float v0 = s0*c2[mt][nt][0] + t0, v1 = s1*c2[mt][nt][1] + t1;
            float v2 = s0*c2[mt][nt][2] + t0, v3 = s1*c2[mt][nt][3] + t1;
            if (relu_out) {
                v0 = fmaxf(v0, 0.f); v1 = fmaxf(v1, 0.f);
                v2 = fmaxf(v2, 0.f); v3 = fmaxf(v3, 0.f);
            }
            *(float2*)&hout[(size_t)row*HDIM + col]     = make_float2(v0, v1);
            *(float2*)&hout[(size_t)(row+8)*HDIM + col] = make_float2(v2, v3);
        }
}

// ================================================================ launch =======
extern "C" void kernel_launch(void* const* d_in, const int* in_sizes, int n_in,
                              void* d_out, int out_size)
{
    const float* x    = (const float*)d_in[0];
    const float* Wt   = (const float*)d_in[2];
    const float* bt   = (const float*)d_in[3];
    const float* W1_0 = (const float*)d_in[4];
    const float* b1_0 = (const float*)d_in[5];
    const float* W2_0 = (const float*)d_in[6];
    const float* b2_0 = (const float*)d_in[7];
    const float* g0   = (const float*)d_in[8];
    const float* be0  = (const float*)d_in[9];
    const float* rm0  = (const float*)d_in[10];
    const float* rv0  = (const float*)d_in[11];
    const float* W1_1 = (const float*)d_in[12];
    const float* b1_1 = (const float*)d_in[13];
    const float* W2_1 = (const float*)d_in[14];
    const float* b2_1 = (const float*)d_in[15];
    const float* g1   = (const float*)d_in[16];
    const float* be1  = (const float*)d_in[17];
    const float* rm1  = (const float*)d_in[18];
    const float* rv1  = (const float*)d_in[19];
    float* out = (float*)d_out;

    cudaFuncSetAttribute(knn_kernel,
                         cudaFuncAttributeMaxDynamicSharedMemorySize, KNN_SMEM_BYTES);
    cudaFuncSetAttribute(gin_mma_kernel,
                         cudaFuncAttributeMaxDynamicSharedMemorySize, GT_SMEM);

    void *p_h0, *p_h1;
    cudaGetSymbolAddress(&p_h0, g_h0);
    cudaGetSymbolAddress(&p_h1, g_h1);

    prep_w_kernel<<<512, 256>>>(W1_0, W2_0, W1_1, W2_1);
    knn_kernel<<<NB*16, KBLK, KNN_SMEM_BYTES>>>(x);
    transfer_kernel<<<(NTOT*HDIM)/256, 256>>>(x, Wt, bt);

    gin_mma_kernel<<<NTOT/GROWS, GT_THREADS, GT_SMEM>>>(
        (const float*)p_h0, (float*)p_h1, 0,
        b1_0, b2_0, g0, be0, rm0, rv0, /*relu_out=*/1);

    gin_mma_kernel<<<NTOT/GROWS, GT_THREADS, GT_SMEM>>>(
        (const float*)p_h1, out, 1,
        b1_1, b2_1, g1, be1, rm1, rv1, /*relu_out=*/0);
}

// round 17
// speedup vs baseline: 1.6394x; 1.6394x over previous
#include <cuda_runtime.h>
#include <cuda_bf16.h>
#include <math.h>
#include <stdint.h>

#define NB   32
#define NP   2048
#define KNN  20
#define HDIM 128
#define HID  256
#define NTOT (NB*NP)
#define EPSBN 1e-5f

// ---------------- scratch (static device globals; no allocation) ----------------
__device__ int   g_nbr[NTOT*KNN];
__device__ float g_h0[(size_t)NTOT*HDIM];
__device__ float g_h1[(size_t)NTOT*HDIM];
// pre-split (bf16 hi/lo), pre-swizzled weights: [layer][half][hi=0/lo=1][128*128]
__device__ __nv_bfloat16 g_w1b[2][2][2][16384];
__device__ __nv_bfloat16 g_w2b[2][2][2][16384];

// ---------------- helpers -------------------------------------------------------
__device__ __forceinline__ uint32_t smem_u32(const void* p) {
    uint32_t a;
    asm("{ .reg .u64 t; cvta.to.shared.u64 t, %1; cvt.u32.u64 %0, t; }" : "=r"(a) : "l"(p));
    return a;
}
__device__ __forceinline__ uint32_t pkbf(float lo, float hi) {
    uint32_t r; asm("cvt.rn.bf16x2.f32 %0, %1, %2;" : "=r"(r) : "f"(hi), "f"(lo)); return r;
}
__device__ __forceinline__ float bfhi(float v) {
    return __bfloat162float(__float2bfloat16_rn(v));
}
__device__ __forceinline__ void mma16816(float (&c)[4], const uint32_t (&a)[4],
                                         uint32_t b0, uint32_t b1) {
    asm volatile(
        "mma.sync.aligned.m16n8k16.row.col.f32.bf16.bf16.f32 "
        "{%0,%1,%2,%3}, {%4,%5,%6,%7}, {%8,%9}, {%0,%1,%2,%3};"
        : "+f"(c[0]), "+f"(c[1]), "+f"(c[2]), "+f"(c[3])
        : "r"(a[0]), "r"(a[1]), "r"(a[2]), "r"(a[3]), "r"(b0), "r"(b1));
}
__device__ __forceinline__ void ldmA(uint32_t (&a)[4], uint32_t base, int m0, int k0, int lane) {
    int row = m0 + (lane & 15);
    int ch  = (k0 >> 3) + (lane >> 4);
    uint32_t addr = base + row*256 + (((ch ^ (row & 7)) & 15) << 4);
    asm volatile("ldmatrix.sync.aligned.m8n8.x4.shared.b16 {%0,%1,%2,%3}, [%4];"
                 : "=r"(a[0]), "=r"(a[1]), "=r"(a[2]), "=r"(a[3]) : "r"(addr));
}
__device__ __forceinline__ void ldmBt(uint32_t (&b)[4], uint32_t base, int k0, int n0, int lane) {
    int k = k0 + (lane & 7) + ((lane >> 3) & 1) * 8;
    int n = n0 + ((lane >> 4) & 1) * 8;
    uint32_t addr = base + k*256 + ((((n >> 3) ^ (k & 7)) & 15) << 4);
    asm volatile("ldmatrix.sync.aligned.m8n8.x4.trans.shared.b16 {%0,%1,%2,%3}, [%4];"
                 : "=r"(b[0]), "=r"(b[1]), "=r"(b[2]), "=r"(b[3]) : "r"(addr));
}

// ================================================================= kNN =========
// R8-proven structure: one query/thread, SMEM broadcast, deferred inserts.
// Local fixes: (1) drains are plain divergent loops (no per-round vote);
// (2) dist stored alongside idx (no recompute in the drain chain);
// (3) replace-max insert (predicated scatter + pairwise max tree, depth 5)
//     instead of the serial 20-deep bubble. Top-20 SET semantics preserved
//     (strict admit, identical to the proven kernel); order is irrelevant to
//     the downstream max-aggregation.
#define KBLK 128
#define KCAP 24
#define KNN_SMEM_BYTES (NP*16 + 2*KCAP*KBLK*4)   // 32K + 24K = 57344 -> 4 blk/SM

__device__ __forceinline__ void knn_drain(const float* __restrict__ sbd,
                                          const int* __restrict__ sbi, int tid,
                                          int &cnt, float (&d)[KNN], int (&id)[KNN],
                                          float &wd, int &wpos)
{
    for (int j = 0; j < cnt; j++) {           // divergent; reconverges naturally
        float dd = sbd[j*KBLK + tid];
        int   ii = sbi[j*KBLK + tid];
        if (dd < wd) {
            // scatter insert at wpos (predicated, no dynamic indexing)
#pragma unroll
            for (int t = 0; t < KNN; t++)
                if (t == wpos) { d[t] = dd; id[t] = ii; }
            // recompute (wd, wpos): pairwise max tree, depth 5
            float mv[KNN]; int mp[KNN];
#pragma unroll
            for (int t = 0; t < KNN; t++) { mv[t] = d[t]; mp[t] = t; }
#pragma unroll
            for (int s = 1; s < KNN; s *= 2)
#pragma unroll
                for (int t = 0; t + s < KNN; t += 2*s)
                    if (mv[t+s] > mv[t]) { mv[t] = mv[t+s]; mp[t] = mp[t+s]; }
            wd = mv[0]; wpos = mp[0];
        }
    }
    cnt = 0;
}

__global__ __launch_bounds__(KBLK)
void knn_kernel(const float* __restrict__ x)
{
    extern __shared__ float4 sc[];            // [NP] 32 KB
    float* sbd = (float*)(sc + NP);           // [KCAP][KBLK] dist stacks
    int*   sbi = (int*)(sbd + KCAP*KBLK);     // [KCAP][KBLK] id stacks
    const int b    = blockIdx.x >> 4;
    const int tile = blockIdx.x & 15;
    const int tid  = threadIdx.x;

    const float* xb = x + (size_t)b*NP*3;
    for (int i = tid; i < NP; i += KBLK) {
        float a0 = xb[i*3+0], a1 = xb[i*3+1], a2 = xb[i*3+2];
        sc[i] = make_float4(a0, a1, a2, a0*a0 + a1*a1 + a2*a2);
    }
    __syncthreads();

    const int q = tile*KBLK + tid;
    const float4 qc = sc[q];

    float d[KNN]; int id[KNN];
#pragma unroll
    for (int j = 0; j < KNN; j++) { d[j] = INFINITY; id[j] = -1; }
    float wd = INFINITY;                      // current worst (max of kept set)
    int   wpos = 0;
    int   cnt = 0;

    for (int c0 = 0; c0 < NP; c0 += 4) {
#pragma unroll
        for (int u = 0; u < 4; u++) {
            int c = c0 + u;
            float4 cc = sc[c];
            float dot  = qc.x*cc.x + qc.y*cc.y + qc.z*cc.z;
            float dist = qc.w + cc.w - 2.0f*dot;   // matches sq_p + sq_q - 2*dot
            if (dist < wd) {                       // cheap predicated push
                sbd[cnt*KBLK + tid] = dist;
                sbi[cnt*KBLK + tid] = c;
                cnt++;
            }
        }
        // synchronized drain entry (amortizes SIMT lockstep across lanes)
        if (__any_sync(0xffffffffu, cnt >= KCAP-4)) {
            knn_drain(sbd, sbi, tid, cnt, d, id, wd, wpos);
        }
    }
    knn_drain(sbd, sbi, tid, cnt, d, id, wd, wpos);

    int* outp = g_nbr + ((size_t)b*NP + q)*KNN;
#pragma unroll
    for (int j = 0; j < KNN; j++) outp[j] = b*NP + id[j];
}

// ============================================================ transfer =========
__global__ void transfer_kernel(const float* __restrict__ x,
                                const float* __restrict__ Wt,
                                const float* __restrict__ bt)
{
    int idx = blockIdx.x * blockDim.x + threadIdx.x;
    int n = idx >> 7, f = idx & (HDIM-1);
    float x0 = x[n*3+0], x1 = x[n*3+1], x2 = x[n*3+2];
    g_h0[idx] = bt[f] + x0*Wt[f] + x1*Wt[HDIM+f] + x2*Wt[2*HDIM+f];
}

// ============================================================ weight prep ======
__global__ void prep_w_kernel(const float* __restrict__ W1_0, const float* __restrict__ W2_0,
                              const float* __restrict__ W1_1, const float* __restrict__ W2_1)
{
    int idx = blockIdx.x * blockDim.x + threadIdx.x;   // 0..131071
    int layer = idx >> 16;
    int rem = idx & 65535;
    const float* W1 = layer ? W1_1 : W1_0;
    const float* W2 = layer ? W2_1 : W2_0;
    if (rem < 32768) {                       // W1 [k=128][n=256]
        int k = rem >> 8, n = rem & 255;
        float v = W1[k*HID + n];
        int h = n >> 7, nl = n & 127;
        int dst = k*128 + (((nl >> 3) ^ (k & 7)) << 3) + (nl & 7);
        __nv_bfloat16 hb = __float2bfloat16_rn(v);
        g_w1b[layer][h][0][dst] = hb;
        g_w1b[layer][h][1][dst] = __float2bfloat16_rn(v - __bfloat162float(hb));
    } else {                                 // W2 [K=256][n=128]
        int r2 = rem - 32768;
        int K = r2 >> 7, n = r2 & 127;
        float v = W2[K*HDIM + n];
        int h = K >> 7, kl = K & 127;
        int dst = kl*128 + (((n >> 3) ^ (kl & 7)) << 3) + (n & 7);
        __nv_bfloat16 hb = __float2bfloat16_rn(v);
        g_w2b[layer][h][0][dst] = hb;
        g_w2b[layer][h][1][dst] = __float2bfloat16_rn(v - __bfloat162float(hb));
    }
}

// ============================================================ GIN layer (mma.sync)
// (byte-identical to the R11 151us/layer win: 128 rows, 512 threads, 4x4 warps)
#define GT_THREADS 512
#define OFF_AHI  2048
#define OFF_ALO  (OFF_AHI + 32768)
#define OFF_THI  (OFF_ALO + 32768)
#define OFF_TLO  (OFF_THI + 32768)
#define OFF_WHI  (OFF_TLO + 32768)
#define OFF_WLO  (OFF_WHI + 32768)
#define GT_SMEM  (OFF_WLO + 32768)           // 198656

__global__ __launch_bounds__(GT_THREADS, 1)
void gin_mma_kernel(const float* __restrict__ hin, float* __restrict__ hout, int layer,
                    const float* __restrict__ b1v, const float* __restrict__ b2v,
                    const float* __restrict__ gw, const float* __restrict__ bb,
                    const float* __restrict__ rm, const float* __restrict__ rv,
                    int relu_out)
{
    extern __shared__ char smem[];
    const uint32_t smb = smem_u32(smem);
    const int tid  = threadIdx.x;
    const int wid  = tid >> 5;
    const int lane = tid & 31;
    const int wm   = wid >> 2;
    const int wn   = wid & 3;
    const int g    = lane >> 2;
    const int t4   = lane & 3;
    const int row0 = blockIdx.x * 128;

    float* s_b1    = (float*)(smem);
    float* s_scale = (float*)(smem + 1024);
    float* s_shift = (float*)(smem + 1536);
    int*   s_nbr   = (int*)(smem + OFF_WHI);

    for (int i = tid; i < HID; i += GT_THREADS) s_b1[i] = b1v[i];
    if (tid < HDIM) {
        float sc = gw[tid] * rsqrtf(rv[tid] + EPSBN);
        s_scale[tid] = sc;
        s_shift[tid] = bb[tid] - sc * rm[tid];
    }
    for (int i = tid; i < 128*KNN; i += GT_THREADS)
        s_nbr[i] = g_nbr[(size_t)row0*KNN + i];
    __syncthreads();

    for (int r = wid; r < 128; r += 16) {
        int row = row0 + r;
        float4 m = __ldg((const float4*)&hin[(size_t)row*HDIM + lane*4]);
#pragma unroll 4
        for (int k = 0; k < KNN; k++) {
            int nb = s_nbr[r*KNN + k];
            float4 v = __ldg((const float4*)&hin[(size_t)nb*HDIM + lane*4]);
            m.x = fmaxf(m.x, v.x); m.y = fmaxf(m.y, v.y);
            m.z = fmaxf(m.z, v.z); m.w = fmaxf(m.w, v.w);
        }
        float h0 = bfhi(m.x), h1 = bfhi(m.y), h2 = bfhi(m.z), h3 = bfhi(m.w);
        int ab = r*256 + ((((lane >> 1) ^ (r & 7)) & 15) << 4) + (lane & 1)*8;
        *(uint2*)(smem + OFF_AHI + ab) = make_uint2(pkbf(m.x, m.y), pkbf(m.z, m.w));
        *(uint2*)(smem + OFF_ALO + ab) =
            make_uint2(pkbf(m.x - h0, m.y - h1), pkbf(m.z - h2, m.w - h3));
    }
    __syncthreads();

    float c2[2][4][4];
#pragma unroll
    for (int mt = 0; mt < 2; mt++)
#pragma unroll
        for (int nt = 0; nt < 4; nt++) {
            int cb = wn*32 + nt*8 + 2*t4;
            c2[mt][nt][0] = b2v[cb];  c2[mt][nt][1] = b2v[cb+1];
            c2[mt][nt][2] = b2v[cb];  c2[mt][nt][3] = b2v[cb+1];
        }

    const uint32_t Ah = smb + OFF_AHI, Al = smb + OFF_ALO;
    const uint32_t Th = smb + OFF_THI, Tl = smb + OFF_TLO;
    const uint32_t Wh = smb + OFF_WHI, Wl = smb + OFF_WLO;

    for (int h = 0; h < 2; h++) {
        {
            const float4* sh = (const float4*)g_w1b[layer][h][0];
            const float4* sl = (const float4*)g_w1b[layer][h][1];
            float4* dh = (float4*)(smem + OFF_WHI);
            float4* dl = (float4*)(smem + OFF_WLO);
            for (int i = tid; i < 2048; i += GT_THREADS) { dh[i] = sh[i]; dl[i] = sl[i]; }
        }
        __syncthreads();

        float c1[2][4][4];
#pragma unroll
        for (int mt = 0; mt < 2; mt++)
#pragma unroll
            for (int nt = 0; nt < 4; nt++) {
                int cb = h*128 + wn*32 + nt*8 + 2*t4;
                c1[mt][nt][0] = s_b1[cb];  c1[mt][nt][1] = s_b1[cb+1];
                c1[mt][nt][2] = s_b1[cb];  c1[mt][nt][3] = s_b1[cb+1];
            }
#pragma unroll
        for (int ks = 0; ks < 8; ks++) {
            uint32_t aH[2][4], aL[2][4];
            ldmA(aH[0], Ah, wm*32,      ks*16, lane);
            ldmA(aH[1], Ah, wm*32 + 16, ks*16, lane);
            ldmA(aL[0], Al, wm*32,      ks*16, lane);
            ldmA(aL[1], Al, wm*32 + 16, ks*16, lane);
#pragma unroll
            for (int np = 0; np < 2; np++) {
                uint32_t bh[4], bl[4];
                ldmBt(bh, Wh, ks*16, wn*32 + np*16, lane);
                ldmBt(bl, Wl, ks*16, wn*32 + np*16, lane);
#pragma unroll
                for (int mt = 0; mt < 2; mt++)
#pragma unroll
                    for (int n2 = 0; n2 < 2; n2++) {
                        int nt = np*2 + n2;
                        mma16816(c1[mt][nt], aH[mt], bh[n2*2], bh[n2*2+1]);
                        mma16816(c1[mt][nt], aL[mt], bh[n2*2], bh[n2*2+1]);
                        mma16816(c1[mt][nt], aH[mt], bl[n2*2], bl[n2*2+1]);
                    }
            }
        }

#pragma unroll
        for (int mt = 0; mt < 2; mt++)
#pragma unroll
            for (int nt = 0; nt < 4; nt++) {
                int r0 = wm*32 + mt*16 + g;
                int r1 = r0 + 8;
                int cl = wn*32 + nt*8 + 2*t4;
                float v0 = fmaxf(c1[mt][nt][0], 0.f), v1 = fmaxf(c1[mt][nt][1], 0.f);
                float v2 = fmaxf(c1[mt][nt][2], 0.f), v3 = fmaxf(c1[mt][nt][3], 0.f);
                float h0 = bfhi(v0), h1 = bfhi(v1), h2 = bfhi(v2), h3 = bfhi(v3);
                int by0 = r0*256 + ((((cl >> 3) ^ (r0 & 7)) & 15) << 4) + (cl & 7)*2;
                int by1 = r1*256 + ((((cl >> 3) ^ (r1 & 7)) & 15) << 4) + (cl & 7)*2;
                *(uint32_t*)(smem + OFF_THI + by0) = pkbf(v0, v1);
                *(uint32_t*)(smem + OFF_TLO + by0) = pkbf(v0 - h0, v1 - h1);
                *(uint32_t*)(smem + OFF_THI + by1) = pkbf(v2, v3);
                *(uint32_t*)(smem + OFF_TLO + by1) = pkbf(v2 - h2, v3 - h3);
            }
        __syncthreads();

        {
            const float4* sh = (const float4*)g_w2b[layer][h][0];
            const float4* sl = (const float4*)g_w2b[layer][h][1];
            float4* dh = (float4*)(smem + OFF_WHI);
            float4* dl = (float4*)(smem + OFF_WLO);
            for (int i = tid; i < 2048; i += GT_THREADS) { dh[i] = sh[i]; dl[i] = sl[i]; }
        }
        __syncthreads();

#pragma unroll
        for (int ks = 0; ks < 8; ks++) {
            uint32_t aH[2][4], aL[2][4];
            ldmA(aH[0], Th, wm*32,      ks*16, lane);
            ldmA(aH[1], Th, wm*32 + 16, ks*16, lane);
            ldmA(aL[0], Tl, wm*32,      ks*16, lane);
            ldmA(aL[1], Tl, wm*32 + 16, ks*16, lane);
#pragma unroll
            for (int np = 0; np < 2; np++) {
                uint32_t bh[4], bl[4];
                ldmBt(bh, Wh, ks*16, wn*32 + np*16, lane);
                ldmBt(bl, Wl, ks*16, wn*32 + np*16, lane);
#pragma unroll
                for (int mt = 0; mt < 2; mt++)
#pragma unroll
                    for (int n2 = 0; n2 < 2; n2++) {
                        int nt = np*2 + n2;
                        mma16816(c2[mt][nt], aH[mt], bh[n2*2], bh[n2*2+1]);
                        mma16816(c2[mt][nt], aL[mt], bh[n2*2], bh[n2*2+1]);
                        mma16816(c2[mt][nt], aH[mt], bl[n2*2], bl[n2*2+1]);
                    }
            }
        }
        __syncthreads();
    }

#pragma unroll
    for (int mt = 0; mt < 2; mt++)
#pragma unroll
        for (int nt = 0; nt < 4; nt++) {
            int row = row0 + wm*32 + mt*16 + g;
            int col = wn*32 + nt*8 + 2*t4;
            float s0 = s_scale[col], s1 = s_scale[col+1];
            float t0 = s_shift[col], t1 = s_shift[col+1];
            float v0 = s0*c2[mt][nt][0] + t0, v1 = s1*c2[mt][nt][1] + t1;
            float v2 = s0*c2[mt][nt][2] + t0, v3 = s1*c2[mt][nt][3] + t1;
            if (relu_out) {
                v0 = fmaxf(v0, 0.f); v1 = fmaxf(v1, 0.f);
                v2 = fmaxf(v2, 0.f); v3 = fmaxf(v3, 0.f);
            }
            *(float2*)&hout[(size_t)row*HDIM + col]     = make_float2(v0, v1);
            *(float2*)&hout[(size_t)(row+8)*HDIM + col] = make_float2(v2, v3);
        }
}

// ================================================================ launch =======
extern "C" void kernel_launch(void* const* d_in, const int* in_sizes, int n_in,
                              void* d_out, int out_size)
{
    const float* x    = (const float*)d_in[0];
    const float* Wt   = (const float*)d_in[2];
    const float* bt   = (const float*)d_in[3];
    const float* W1_0 = (const float*)d_in[4];
    const float* b1_0 = (const float*)d_in[5];
    const float* W2_0 = (const float*)d_in[6];
    const float* b2_0 = (const float*)d_in[7];
    const float* g0   = (const float*)d_in[8];
    const float* be0  = (const float*)d_in[9];
    const float* rm0  = (const float*)d_in[10];
    const float* rv0  = (const float*)d_in[11];
    const float* W1_1 = (const float*)d_in[12];
    const float* b1_1 = (const float*)d_in[13];
    const float* W2_1 = (const float*)d_in[14];
    const float* b2_1 = (const float*)d_in[15];
    const float* g1   = (const float*)d_in[16];
    const float* be1  = (const float*)d_in[17];
    const float* rm1  = (const float*)d_in[18];
    const float* rv1  = (const float*)d_in[19];
    float* out = (float*)d_out;

    cudaFuncSetAttribute(knn_kernel,
                         cudaFuncAttributeMaxDynamicSharedMemorySize, KNN_SMEM_BYTES);
    cudaFuncSetAttribute(gin_mma_kernel,
                         cudaFuncAttributeMaxDynamicSharedMemorySize, GT_SMEM);

    void *p_h0, *p_h1;
    cudaGetSymbolAddress(&p_h0, g_h0);
    cudaGetSymbolAddress(&p_h1, g_h1);

    prep_w_kernel<<<512, 256>>>(W1_0, W2_0, W1_1, W2_1);
    knn_kernel<<<NB*16, KBLK, KNN_SMEM_BYTES>>>(x);
    transfer_kernel<<<(NTOT*HDIM)/256, 256>>>(x, Wt, bt);

    gin_mma_kernel<<<NTOT/128, GT_THREADS, GT_SMEM>>>(
        (const float*)p_h0, (float*)p_h1, 0,
        b1_0, b2_0, g0, be0, rm0, rv0, /*relu_out=*/1);

    gin_mma_kernel<<<NTOT/128, GT_THREADS, GT_SMEM>>>(
        (const float*)p_h1, out, 1,
        b1_1, b2_1, g1, be1, rm1, rv1, /*relu_out=*/0);
}